// round 6
// baseline (speedup 1.0000x reference)
#include <cuda_runtime.h>
#include <cstdint>

#define NUM_RULES 729
#define BLOCK     256          // 8 warps; warp covers 16 batch rows per group
#define GRID      128          // 128 CTAs * 2 groups * 128 rows = 32768
#define NCHUNK    108          // k8 chunks: K = 27 o-blocks * 32 = 864
#define FRAG_ELEMS (NCHUNK * 32)
#define SMEM_BYTES (FRAG_ELEMS * 16)   // 55296 B dynamic

__device__ __forceinline__ uint32_t tf32_of(float f) {
    uint32_t r;
    asm("cvt.rn.tf32.f32 %0, %1;" : "=r"(r) : "f"(f));
    return r;
}

__device__ __forceinline__ void mma_tf32(float* d, const uint32_t* a,
                                         uint32_t b0, uint32_t b1) {
    asm("mma.sync.aligned.m16n8k8.row.col.f32.tf32.tf32.f32 "
        "{%0,%1,%2,%3}, {%4,%5,%6,%7}, {%8,%9}, {%0,%1,%2,%3};"
        : "+f"(d[0]), "+f"(d[1]), "+f"(d[2]), "+f"(d[3])
        : "r"(a[0]), "r"(a[1]), "r"(a[2]), "r"(a[3]), "r"(b0), "r"(b1));
}

// cons element: component m (0..15 = [kp0..6, 1, ki0..6, 0]), padded-k (0..863)
__device__ __forceinline__ float cons_val(const float* __restrict__ kp,
                                          const float* __restrict__ ki,
                                          int m, int k) {
    const int o  = k >> 5;
    const int kk = k & 31;
    if (kk >= 27) return 0.0f;          // o-block padding
    const int r = o * 27 + kk;
    if (m == 7)  return 1.0f;           // wsum row
    if (m == 15) return 0.0f;
    if (m < 7)   return kp[r * 7 + m];
    return ki[r * 7 + (m - 8)];
}

// memberships -> t012[27] (local mem, runtime-indexed) + this lane's 8 t345
// factors s[n] = t345[j + 4n]  (j = lane & 3)
__device__ __forceinline__ void row_setup(const float* __restrict__ x,
                                          const float* __restrict__ means,
                                          const float* __restrict__ sigmas,
                                          int row, int j,
                                          float* t012, float* s) {
    float xv[6];
    #pragma unroll
    for (int i = 0; i < 6; i++) xv[i] = x[row * 6 + i];

    float mu[6][3];
    #pragma unroll
    for (int i = 0; i < 6; i++)
        #pragma unroll
        for (int m = 0; m < 3; m++) {
            const float rs = __fdividef(1.0f, sigmas[i * 3 + m] + 1e-6f);
            const float t  = (xv[i] - means[i * 3 + m]) * rs;
            mu[i][m] = __expf(-0.5f * t * t);
        }

    #pragma unroll
    for (int a = 0; a < 3; a++)
        #pragma unroll
        for (int b = 0; b < 3; b++)
            #pragma unroll
            for (int d = 0; d < 3; d++)
                t012[a * 9 + b * 3 + d] = mu[0][a] * mu[1][b] * mu[2][d];

    #pragma unroll
    for (int n = 0; n < 8; n++) {
        const int i = j + 4 * n;
        s[n] = (i < 27) ? mu[3][i / 9] * mu[4][(i % 9) / 3] * mu[5][i % 3] : 0.0f;
    }
}

__global__ __launch_bounds__(BLOCK)
void anfis_tf32_kernel(const float* __restrict__ x,
                       const float* __restrict__ means,
                       const float* __restrict__ sigmas,
                       const float* __restrict__ cons_kp,
                       const float* __restrict__ cons_ki,
                       float* __restrict__ out) {
    extern __shared__ uint4 cons_frag[];        // [NCHUNK*32], tf32 A fragments
    __shared__ float vbuf[8][16][17];           // +1 pad: conflict-free epilogue

    const int tid = threadIdx.x;
    const int w   = tid >> 5;
    const int l   = tid & 31;
    const int j   = l & 3;        // threadID-in-group (k position)
    const int g   = l >> 2;       // groupID (batch row within n-tile / comp row)

    // ---- build tf32 A-fragment table in exact mma order ----
    for (int e = tid; e < FRAG_ELEMS; e += BLOCK) {
        const int C  = e >> 5;          // chunk
        const int el = e & 31;
        const int ej = el & 3;
        const int eg = el >> 2;
        const int k0 = C * 8;
        uint4 v;
        v.x = tf32_of(cons_val(cons_kp, cons_ki, eg,     k0 + ej));
        v.y = tf32_of(cons_val(cons_kp, cons_ki, eg + 8, k0 + ej));
        v.z = tf32_of(cons_val(cons_kp, cons_ki, eg,     k0 + ej + 4));
        v.w = tf32_of(cons_val(cons_kp, cons_ki, eg + 8, k0 + ej + 4));
        cons_frag[e] = v;
    }
    __syncthreads();

    #pragma unroll 1
    for (int grp = 0; grp < 2; grp++) {
        const int Rbase = blockIdx.x * 256 + grp * 128 + w * 16;
        const int rA = Rbase + g;       // n-tile A: batch rows Rbase..+7
        const int rB = rA + 8;          // n-tile B: batch rows Rbase+8..+15

        float t012A[27], t012B[27], sA[8], sB[8];
        row_setup(x, means, sigmas, rA, j, t012A, sA);
        row_setup(x, means, sigmas, rB, j, t012B, sB);

        float dA[4] = {0.f, 0.f, 0.f, 0.f};
        float dB[4] = {0.f, 0.f, 0.f, 0.f};

        #pragma unroll 1
        for (int o = 0; o < 27; o++) {
            const float qA = t012A[o];
            const float qB = t012B[o];
            #pragma unroll
            for (int c = 0; c < 4; c++) {
                uint4 a = cons_frag[(o * 4 + c) * 32 + l];
                const uint32_t bA0 = tf32_of(qA * sA[2 * c]);
                const uint32_t bA1 = tf32_of(qA * sA[2 * c + 1]);
                mma_tf32(dA, &a.x, bA0, bA1);
                const uint32_t bB0 = tf32_of(qB * sB[2 * c]);
                const uint32_t bB1 = tf32_of(qB * sB[2 * c + 1]);
                mma_tf32(dB, &a.x, bB0, bB1);
            }
        }

        // ---- scatter D fragments: vbuf[w][batch_n][comp] ----
        // d0=D[g][2j], d1=D[g][2j+1], d2=D[g+8][2j], d3=D[g+8][2j+1]
        __syncwarp();                 // prev group's epilogue reads done
        const int jj = 2 * j;
        vbuf[w][jj][g]         = dA[0];
        vbuf[w][jj + 1][g]     = dA[1];
        vbuf[w][jj][g + 8]     = dA[2];
        vbuf[w][jj + 1][g + 8] = dA[3];
        vbuf[w][8 + jj][g]         = dB[0];
        vbuf[w][8 + jj + 1][g]     = dB[1];
        vbuf[w][8 + jj][g + 8]     = dB[2];
        vbuf[w][8 + jj + 1][g + 8] = dB[3];
        __syncwarp();

        // ---- epilogue: lanes 0..15 finish one batch row each ----
        if (l < 16) {
            const float* v = vbuf[w][l];
            const int row = Rbase + l;
            float xv[6];
            #pragma unroll
            for (int i = 0; i < 6; i++) xv[i] = x[row * 6 + i];

            const float rden = 1.0f / (v[7] + 1e-6f);
            float skp = v[6], ski = v[14];
            #pragma unroll
            for (int i = 0; i < 6; i++) {
                skp = fmaf(xv[i], v[i],     skp);
                ski = fmaf(xv[i], v[8 + i], ski);
            }
            float2 res;
            res.x = skp * rden;
            res.y = ski * rden;
            *reinterpret_cast<float2*>(out + 2 * row) = res;
        }
    }
}

extern "C" void kernel_launch(void* const* d_in, const int* in_sizes, int n_in,
                              void* d_out, int out_size) {
    const float* x       = (const float*)d_in[0];
    const float* means   = (const float*)d_in[1];
    const float* sigmas  = (const float*)d_in[2];
    const float* cons_kp = (const float*)d_in[3];
    const float* cons_ki = (const float*)d_in[4];
    // d_in[5] = rule_idx: deterministic base-3 digits, baked into the k-permutation
    float* out = (float*)d_out;
    cudaFuncSetAttribute(anfis_tf32_kernel,
                         cudaFuncAttributeMaxDynamicSharedMemorySize, SMEM_BYTES);
    anfis_tf32_kernel<<<GRID, BLOCK, SMEM_BYTES>>>(x, means, sigmas,
                                                   cons_kp, cons_ki, out);
}

// round 7
// speedup vs baseline: 1.3879x; 1.3879x over previous
#include <cuda_runtime.h>
#include <cstdint>

#define NUM_RULES 729
#define BLOCK     512          // 16 warps; each warp 16 batch rows; CTA = 256 rows
#define GRID      128          // 128 CTAs * 256 rows = 32768
#define NCHUNK    108          // k8 chunks: K = 27 o-blocks * 32 = 864
#define FRAG_ELEMS (NCHUNK * 32)
#define SMEM_BYTES (FRAG_ELEMS * 16)   // 55296 B dynamic

__device__ __forceinline__ uint32_t tf32_of(float f) {
    uint32_t r;
    asm("cvt.rn.tf32.f32 %0, %1;" : "=r"(r) : "f"(f));
    return r;
}

__device__ __forceinline__ void mma_tf32(float* d, const uint32_t* a,
                                         uint32_t b0, uint32_t b1) {
    asm("mma.sync.aligned.m16n8k8.row.col.f32.tf32.tf32.f32 "
        "{%0,%1,%2,%3}, {%4,%5,%6,%7}, {%8,%9}, {%0,%1,%2,%3};"
        : "+f"(d[0]), "+f"(d[1]), "+f"(d[2]), "+f"(d[3])
        : "r"(a[0]), "r"(a[1]), "r"(a[2]), "r"(a[3]), "r"(b0), "r"(b1));
}

// cons element: component m (0..15 = [kp0..6, 1, ki0..6, 0]), padded-k (0..863)
__device__ __forceinline__ float cons_val(const float* __restrict__ kp,
                                          const float* __restrict__ ki,
                                          int m, int k) {
    const int o  = k >> 5;
    const int kk = k & 31;
    if (kk >= 27) return 0.0f;          // o-block padding
    const int r = o * 27 + kk;
    if (m == 7)  return 1.0f;           // wsum row
    if (m == 15) return 0.0f;
    if (m < 7)   return kp[r * 7 + m];
    return ki[r * 7 + (m - 8)];
}

// memberships -> t012[27] (local, runtime-indexed) + this lane's 8 t345
// factors s[n] = t345[j + 4n]  (j = lane & 3)
__device__ __forceinline__ void row_setup(const float* __restrict__ x,
                                          const float* __restrict__ means,
                                          const float* __restrict__ sigmas,
                                          int row, int j,
                                          float* t012, float* s) {
    float xv[6];
    #pragma unroll
    for (int i = 0; i < 6; i++) xv[i] = x[row * 6 + i];

    float mu[6][3];
    #pragma unroll
    for (int i = 0; i < 6; i++)
        #pragma unroll
        for (int m = 0; m < 3; m++) {
            const float rs = __fdividef(1.0f, sigmas[i * 3 + m] + 1e-6f);
            const float t  = (xv[i] - means[i * 3 + m]) * rs;
            mu[i][m] = __expf(-0.5f * t * t);
        }

    #pragma unroll
    for (int a = 0; a < 3; a++)
        #pragma unroll
        for (int b = 0; b < 3; b++)
            #pragma unroll
            for (int d = 0; d < 3; d++)
                t012[a * 9 + b * 3 + d] = mu[0][a] * mu[1][b] * mu[2][d];

    #pragma unroll
    for (int n = 0; n < 8; n++) {
        const int i = j + 4 * n;
        s[n] = (i < 27) ? mu[3][i / 9] * mu[4][(i % 9) / 3] * mu[5][i % 3] : 0.0f;
    }
}

__global__ __launch_bounds__(BLOCK)
void anfis_tf32_kernel(const float* __restrict__ x,
                       const float* __restrict__ means,
                       const float* __restrict__ sigmas,
                       const float* __restrict__ cons_kp,
                       const float* __restrict__ cons_ki,
                       float* __restrict__ out) {
    extern __shared__ uint4 cons_frag[];        // [NCHUNK*32], tf32 A fragments
    __shared__ float vbuf[16][16][17];          // +1 pad: conflict-free epilogue

    const int tid = threadIdx.x;
    const int w   = tid >> 5;
    const int l   = tid & 31;
    const int j   = l & 3;        // threadID-in-group (k position)
    const int g   = l >> 2;       // groupID (batch row within n-tile / comp row)

    // ---- build tf32 A-fragment table in exact mma order ----
    for (int e = tid; e < FRAG_ELEMS; e += BLOCK) {
        const int C  = e >> 5;          // chunk
        const int el = e & 31;
        const int ej = el & 3;
        const int eg = el >> 2;
        const int k0 = C * 8;
        uint4 v;
        v.x = tf32_of(cons_val(cons_kp, cons_ki, eg,     k0 + ej));
        v.y = tf32_of(cons_val(cons_kp, cons_ki, eg + 8, k0 + ej));
        v.z = tf32_of(cons_val(cons_kp, cons_ki, eg,     k0 + ej + 4));
        v.w = tf32_of(cons_val(cons_kp, cons_ki, eg + 8, k0 + ej + 4));
        cons_frag[e] = v;
    }

    // ---- per-thread rows: two n8 tiles per warp (16 rows) ----
    const int Rbase = blockIdx.x * 256 + w * 16;
    const int rA = Rbase + g;       // n-tile A: rows Rbase..+7
    const int rB = rA + 8;          // n-tile B: rows Rbase+8..+15

    float t012A[27], t012B[27], sA[8], sB[8];
    row_setup(x, means, sigmas, rA, j, t012A, sA);
    row_setup(x, means, sigmas, rB, j, t012B, sB);

    __syncthreads();   // cons_frag ready

    // ---- main loop: 4 independent accumulator chains ----
    float dA0[4] = {0.f,0.f,0.f,0.f}, dA1[4] = {0.f,0.f,0.f,0.f};
    float dB0[4] = {0.f,0.f,0.f,0.f}, dB1[4] = {0.f,0.f,0.f,0.f};

    #pragma unroll 1
    for (int o = 0; o < 27; o++) {
        const float qA = t012A[o];
        const float qB = t012B[o];

        // hoist all b-operand cvts off the MMA critical path
        uint32_t bA[8], bB[8];
        #pragma unroll
        for (int n = 0; n < 8; n++) {
            bA[n] = tf32_of(qA * sA[n]);
            bB[n] = tf32_of(qB * sB[n]);
        }
        // hoist the 4 a-fragment loads (shared by both row tiles)
        uint4 a0 = cons_frag[(o * 4 + 0) * 32 + l];
        uint4 a1 = cons_frag[(o * 4 + 1) * 32 + l];
        uint4 a2 = cons_frag[(o * 4 + 2) * 32 + l];
        uint4 a3 = cons_frag[(o * 4 + 3) * 32 + l];

        mma_tf32(dA0, &a0.x, bA[0], bA[1]);
        mma_tf32(dB0, &a0.x, bB[0], bB[1]);
        mma_tf32(dA1, &a1.x, bA[2], bA[3]);
        mma_tf32(dB1, &a1.x, bB[2], bB[3]);
        mma_tf32(dA0, &a2.x, bA[4], bA[5]);
        mma_tf32(dB0, &a2.x, bB[4], bB[5]);
        mma_tf32(dA1, &a3.x, bA[6], bA[7]);
        mma_tf32(dB1, &a3.x, bB[6], bB[7]);
    }

    float dA[4], dB[4];
    #pragma unroll
    for (int i = 0; i < 4; i++) { dA[i] = dA0[i] + dA1[i]; dB[i] = dB0[i] + dB1[i]; }

    // ---- scatter D fragments: vbuf[w][batch_n][comp] ----
    // d0=D[g][2j], d1=D[g][2j+1], d2=D[g+8][2j], d3=D[g+8][2j+1]
    const int jj = 2 * j;
    vbuf[w][jj][g]         = dA[0];
    vbuf[w][jj + 1][g]     = dA[1];
    vbuf[w][jj][g + 8]     = dA[2];
    vbuf[w][jj + 1][g + 8] = dA[3];
    vbuf[w][8 + jj][g]         = dB[0];
    vbuf[w][8 + jj + 1][g]     = dB[1];
    vbuf[w][8 + jj][g + 8]     = dB[2];
    vbuf[w][8 + jj + 1][g + 8] = dB[3];
    __syncwarp();

    // ---- epilogue: lanes 0..15 finish one batch row each ----
    if (l < 16) {
        const float* v = vbuf[w][l];
        const int row = Rbase + l;
        float xv[6];
        #pragma unroll
        for (int i = 0; i < 6; i++) xv[i] = x[row * 6 + i];

        const float rden = 1.0f / (v[7] + 1e-6f);
        float skp = v[6], ski = v[14];
        #pragma unroll
        for (int i = 0; i < 6; i++) {
            skp = fmaf(xv[i], v[i],     skp);
            ski = fmaf(xv[i], v[8 + i], ski);
        }
        float2 res;
        res.x = skp * rden;
        res.y = ski * rden;
        *reinterpret_cast<float2*>(out + 2 * row) = res;
    }
}

extern "C" void kernel_launch(void* const* d_in, const int* in_sizes, int n_in,
                              void* d_out, int out_size) {
    const float* x       = (const float*)d_in[0];
    const float* means   = (const float*)d_in[1];
    const float* sigmas  = (const float*)d_in[2];
    const float* cons_kp = (const float*)d_in[3];
    const float* cons_ki = (const float*)d_in[4];
    // d_in[5] = rule_idx: deterministic base-3 digits, baked into the k-permutation
    float* out = (float*)d_out;
    cudaFuncSetAttribute(anfis_tf32_kernel,
                         cudaFuncAttributeMaxDynamicSharedMemorySize, SMEM_BYTES);
    anfis_tf32_kernel<<<GRID, BLOCK, SMEM_BYTES>>>(x, means, sigmas,
                                                   cons_kp, cons_ki, out);
}

// round 8
// speedup vs baseline: 1.4631x; 1.0542x over previous
#include <cuda_runtime.h>
#include <cstdint>

#define NUM_RULES 729
#define BLOCK     512          // 16 warps; each warp 16 batch rows; CTA = 256 rows
#define GRID      128          // 128 CTAs * 256 rows = 32768
#define NCHUNK    108          // k8 chunks: K = 27 o-blocks * 32 = 864
#define FRAG_ELEMS (NCHUNK * 32)
#define SMEM_BYTES (FRAG_ELEMS * 16)   // 55296 B dynamic

__device__ __forceinline__ uint32_t tf32_of(float f) {
    uint32_t r;
    asm("cvt.rn.tf32.f32 %0, %1;" : "=r"(r) : "f"(f));
    return r;
}

// tf32 mma; b operands are raw f32 bit patterns (hardware reads top 19 bits,
// i.e. round-toward-zero tf32 — error ~1e-5, margin is 250x)
__device__ __forceinline__ void mma_tf32(float* d, const uint32_t* a,
                                         float b0f, float b1f) {
    const uint32_t b0 = __float_as_uint(b0f);
    const uint32_t b1 = __float_as_uint(b1f);
    asm("mma.sync.aligned.m16n8k8.row.col.f32.tf32.tf32.f32 "
        "{%0,%1,%2,%3}, {%4,%5,%6,%7}, {%8,%9}, {%0,%1,%2,%3};"
        : "+f"(d[0]), "+f"(d[1]), "+f"(d[2]), "+f"(d[3])
        : "r"(a[0]), "r"(a[1]), "r"(a[2]), "r"(a[3]), "r"(b0), "r"(b1));
}

// cons element: component m (0..15 = [kp0..6, 1, ki0..6, 0]), padded-k (0..863)
__device__ __forceinline__ float cons_val(const float* __restrict__ kp,
                                          const float* __restrict__ ki,
                                          int m, int k) {
    const int o  = k >> 5;
    const int kk = k & 31;
    if (kk >= 27) return 0.0f;          // o-block padding
    const int r = o * 27 + kk;
    if (m == 7)  return 1.0f;           // wsum row
    if (m == 15) return 0.0f;
    if (m < 7)   return kp[r * 7 + m];
    return ki[r * 7 + (m - 8)];
}

// memberships -> t012[27] (local, runtime-indexed) + this lane's 8 t345
// factors s[n] = t345[j + 4n]  (j = lane & 3)
__device__ __forceinline__ void row_setup(const float* __restrict__ x,
                                          const float* __restrict__ means,
                                          const float* __restrict__ sigmas,
                                          int row, int j,
                                          float* t012, float* s) {
    float xv[6];
    #pragma unroll
    for (int i = 0; i < 6; i++) xv[i] = x[row * 6 + i];

    float mu[6][3];
    #pragma unroll
    for (int i = 0; i < 6; i++)
        #pragma unroll
        for (int m = 0; m < 3; m++) {
            const float rs = __fdividef(1.0f, sigmas[i * 3 + m] + 1e-6f);
            const float t  = (xv[i] - means[i * 3 + m]) * rs;
            mu[i][m] = __expf(-0.5f * t * t);
        }

    #pragma unroll
    for (int a = 0; a < 3; a++)
        #pragma unroll
        for (int b = 0; b < 3; b++)
            #pragma unroll
            for (int d = 0; d < 3; d++)
                t012[a * 9 + b * 3 + d] = mu[0][a] * mu[1][b] * mu[2][d];

    #pragma unroll
    for (int n = 0; n < 8; n++) {
        const int i = j + 4 * n;
        s[n] = (i < 27) ? mu[3][i / 9] * mu[4][(i % 9) / 3] * mu[5][i % 3] : 0.0f;
    }
}

__global__ __launch_bounds__(BLOCK, 1)
void anfis_tf32_kernel(const float* __restrict__ x,
                       const float* __restrict__ means,
                       const float* __restrict__ sigmas,
                       const float* __restrict__ cons_kp,
                       const float* __restrict__ cons_ki,
                       float* __restrict__ out) {
    extern __shared__ uint4 cons_frag[];        // [NCHUNK*32], tf32 A fragments
    __shared__ float vbuf[16][16][17];          // +1 pad: conflict-free epilogue

    const int tid = threadIdx.x;
    const int w   = tid >> 5;
    const int l   = tid & 31;
    const int j   = l & 3;        // threadID-in-group (k position)
    const int g   = l >> 2;       // groupID (batch row within n-tile / comp row)

    // ---- build tf32 A-fragment table in exact mma order ----
    for (int e = tid; e < FRAG_ELEMS; e += BLOCK) {
        const int C  = e >> 5;          // chunk
        const int el = e & 31;
        const int ej = el & 3;
        const int eg = el >> 2;
        const int k0 = C * 8;
        uint4 v;
        v.x = tf32_of(cons_val(cons_kp, cons_ki, eg,     k0 + ej));
        v.y = tf32_of(cons_val(cons_kp, cons_ki, eg + 8, k0 + ej));
        v.z = tf32_of(cons_val(cons_kp, cons_ki, eg,     k0 + ej + 4));
        v.w = tf32_of(cons_val(cons_kp, cons_ki, eg + 8, k0 + ej + 4));
        cons_frag[e] = v;
    }

    // ---- per-thread rows: two n8 tiles per warp (16 rows) ----
    const int Rbase = blockIdx.x * 256 + w * 16;
    const int rA = Rbase + g;       // n-tile A: rows Rbase..+7
    const int rB = rA + 8;          // n-tile B: rows Rbase+8..+15

    float t012A[27], t012B[27], sA[8], sB[8];
    row_setup(x, means, sigmas, rA, j, t012A, sA);
    row_setup(x, means, sigmas, rB, j, t012B, sB);

    __syncthreads();   // cons_frag ready

    // ---- main loop: 4 independent accumulator chains ----
    float dA0[4] = {0.f,0.f,0.f,0.f}, dA1[4] = {0.f,0.f,0.f,0.f};
    float dB0[4] = {0.f,0.f,0.f,0.f}, dB1[4] = {0.f,0.f,0.f,0.f};

    #pragma unroll 1
    for (int o = 0; o < 27; o++) {
        const float qA = t012A[o];
        const float qB = t012B[o];

        // b operands: plain FMUL, no cvt (raw f32 bits -> tf32 truncation)
        float bA[8], bB[8];
        #pragma unroll
        for (int n = 0; n < 8; n++) {
            bA[n] = qA * sA[n];
            bB[n] = qB * sB[n];
        }
        // hoist the 4 a-fragment loads (shared by both row tiles)
        uint4 a0 = cons_frag[(o * 4 + 0) * 32 + l];
        uint4 a1 = cons_frag[(o * 4 + 1) * 32 + l];
        uint4 a2 = cons_frag[(o * 4 + 2) * 32 + l];
        uint4 a3 = cons_frag[(o * 4 + 3) * 32 + l];

        mma_tf32(dA0, &a0.x, bA[0], bA[1]);
        mma_tf32(dB0, &a0.x, bB[0], bB[1]);
        mma_tf32(dA1, &a1.x, bA[2], bA[3]);
        mma_tf32(dB1, &a1.x, bB[2], bB[3]);
        mma_tf32(dA0, &a2.x, bA[4], bA[5]);
        mma_tf32(dB0, &a2.x, bB[4], bB[5]);
        mma_tf32(dA1, &a3.x, bA[6], bA[7]);
        mma_tf32(dB1, &a3.x, bB[6], bB[7]);
    }

    float dA[4], dB[4];
    #pragma unroll
    for (int i = 0; i < 4; i++) { dA[i] = dA0[i] + dA1[i]; dB[i] = dB0[i] + dB1[i]; }

    // ---- scatter D fragments: vbuf[w][batch_n][comp] ----
    // d0=D[g][2j], d1=D[g][2j+1], d2=D[g+8][2j], d3=D[g+8][2j+1]
    const int jj = 2 * j;
    vbuf[w][jj][g]         = dA[0];
    vbuf[w][jj + 1][g]     = dA[1];
    vbuf[w][jj][g + 8]     = dA[2];
    vbuf[w][jj + 1][g + 8] = dA[3];
    vbuf[w][8 + jj][g]         = dB[0];
    vbuf[w][8 + jj + 1][g]     = dB[1];
    vbuf[w][8 + jj][g + 8]     = dB[2];
    vbuf[w][8 + jj + 1][g + 8] = dB[3];
    __syncwarp();

    // ---- epilogue: lanes 0..15 finish one batch row each ----
    if (l < 16) {
        const float* v = vbuf[w][l];
        const int row = Rbase + l;
        float xv[6];
        #pragma unroll
        for (int i = 0; i < 6; i++) xv[i] = x[row * 6 + i];

        const float rden = 1.0f / (v[7] + 1e-6f);
        float skp = v[6], ski = v[14];
        #pragma unroll
        for (int i = 0; i < 6; i++) {
            skp = fmaf(xv[i], v[i],     skp);
            ski = fmaf(xv[i], v[8 + i], ski);
        }
        float2 res;
        res.x = skp * rden;
        res.y = ski * rden;
        *reinterpret_cast<float2*>(out + 2 * row) = res;
    }
}

extern "C" void kernel_launch(void* const* d_in, const int* in_sizes, int n_in,
                              void* d_out, int out_size) {
    const float* x       = (const float*)d_in[0];
    const float* means   = (const float*)d_in[1];
    const float* sigmas  = (const float*)d_in[2];
    const float* cons_kp = (const float*)d_in[3];
    const float* cons_ki = (const float*)d_in[4];
    // d_in[5] = rule_idx: deterministic base-3 digits, baked into the k-permutation
    float* out = (float*)d_out;
    cudaFuncSetAttribute(anfis_tf32_kernel,
                         cudaFuncAttributeMaxDynamicSharedMemorySize, SMEM_BYTES);
    anfis_tf32_kernel<<<GRID, BLOCK, SMEM_BYTES>>>(x, means, sigmas,
                                                   cons_kp, cons_ki, out);
}

// round 9
// speedup vs baseline: 1.7368x; 1.1871x over previous
#include <cuda_runtime.h>
#include <cstdint>

#define NUM_RULES 729
#define BLOCK     512          // 16 warps; each warp 16 batch rows; CTA = 256 rows
#define GRID      128          // 128 CTAs * 256 rows = 32768
#define NCHUNK    108          // k8 chunks: K = 27 o-blocks * 32 = 864
#define FRAG_ELEMS (NCHUNK * 32)
#define SMEM_BYTES (FRAG_ELEMS * 16)   // 55296 B dynamic

__device__ __forceinline__ uint32_t tf32_of(float f) {
    uint32_t r;
    asm("cvt.rn.tf32.f32 %0, %1;" : "=r"(r) : "f"(f));
    return r;
}

// tf32 mma; b operands are raw f32 bit patterns (hardware reads top 19 bits,
// i.e. round-toward-zero tf32 — measured error ~4e-6, margin 250x)
__device__ __forceinline__ void mma_tf32(float* d, const uint32_t* a,
                                         float b0f, float b1f) {
    const uint32_t b0 = __float_as_uint(b0f);
    const uint32_t b1 = __float_as_uint(b1f);
    asm("mma.sync.aligned.m16n8k8.row.col.f32.tf32.tf32.f32 "
        "{%0,%1,%2,%3}, {%4,%5,%6,%7}, {%8,%9}, {%0,%1,%2,%3};"
        : "+f"(d[0]), "+f"(d[1]), "+f"(d[2]), "+f"(d[3])
        : "r"(a[0]), "r"(a[1]), "r"(a[2]), "r"(a[3]), "r"(b0), "r"(b1));
}

// cons element: component m (0..15 = [kp0..6, 1, ki0..6, 0]), padded-k (0..863)
__device__ __forceinline__ float cons_val(const float* __restrict__ kp,
                                          const float* __restrict__ ki,
                                          int m, int k) {
    const int o  = k >> 5;
    const int kk = k & 31;
    if (kk >= 27) return 0.0f;          // o-block padding
    const int r = o * 27 + kk;
    if (m == 7)  return 1.0f;           // wsum row
    if (m == 15) return 0.0f;
    if (m < 7)   return kp[r * 7 + m];
    return ki[r * 7 + (m - 8)];
}

// memberships -> m01[9] (mu0*mu1), mu2[3], and this lane's 8 t345 factors
// s[n] = t345[j + 4n]  (j = lane & 3).  All register-resident (constant idx).
__device__ __forceinline__ void row_setup(const float* __restrict__ x,
                                          const float* __restrict__ means,
                                          const float* __restrict__ sigmas,
                                          int row, int j,
                                          float* m01, float* mu2, float* s) {
    float xv[6];
    #pragma unroll
    for (int i = 0; i < 6; i++) xv[i] = x[row * 6 + i];

    float mu[6][3];
    #pragma unroll
    for (int i = 0; i < 6; i++)
        #pragma unroll
        for (int m = 0; m < 3; m++) {
            const float rs = __fdividef(1.0f, sigmas[i * 3 + m] + 1e-6f);
            const float t  = (xv[i] - means[i * 3 + m]) * rs;
            mu[i][m] = __expf(-0.5f * t * t);
        }

    #pragma unroll
    for (int a = 0; a < 3; a++)
        #pragma unroll
        for (int b = 0; b < 3; b++)
            m01[a * 3 + b] = mu[0][a] * mu[1][b];
    #pragma unroll
    for (int d = 0; d < 3; d++) mu2[d] = mu[2][d];

    #pragma unroll
    for (int n = 0; n < 8; n++) {
        const int i = j + 4 * n;
        s[n] = (i < 27) ? mu[3][i / 9] * mu[4][(i % 9) / 3] * mu[5][i % 3] : 0.0f;
    }
}

__global__ __launch_bounds__(BLOCK, 1)
void anfis_tf32_kernel(const float* __restrict__ x,
                       const float* __restrict__ means,
                       const float* __restrict__ sigmas,
                       const float* __restrict__ cons_kp,
                       const float* __restrict__ cons_ki,
                       float* __restrict__ out) {
    extern __shared__ uint4 cons_frag[];        // [NCHUNK*32], tf32 A fragments
    __shared__ float vbuf[16][16][17];          // +1 pad: conflict-free epilogue

    const int tid = threadIdx.x;
    const int w   = tid >> 5;
    const int l   = tid & 31;
    const int j   = l & 3;        // threadID-in-group (k position)
    const int g   = l >> 2;       // groupID (batch row within n-tile / comp row)

    // ---- build tf32 A-fragment table in exact mma order ----
    for (int e = tid; e < FRAG_ELEMS; e += BLOCK) {
        const int C  = e >> 5;          // chunk
        const int el = e & 31;
        const int ej = el & 3;
        const int eg = el >> 2;
        const int k0 = C * 8;
        uint4 v;
        v.x = tf32_of(cons_val(cons_kp, cons_ki, eg,     k0 + ej));
        v.y = tf32_of(cons_val(cons_kp, cons_ki, eg + 8, k0 + ej));
        v.z = tf32_of(cons_val(cons_kp, cons_ki, eg,     k0 + ej + 4));
        v.w = tf32_of(cons_val(cons_kp, cons_ki, eg + 8, k0 + ej + 4));
        cons_frag[e] = v;
    }

    // ---- per-thread rows: two n8 tiles per warp (16 rows) ----
    const int Rbase = blockIdx.x * 256 + w * 16;
    const int rA = Rbase + g;       // n-tile A: rows Rbase..+7
    const int rB = rA + 8;          // n-tile B: rows Rbase+8..+15

    float m01A[9], mu2A[3], sA[8];
    float m01B[9], mu2B[3], sB[8];
    row_setup(x, means, sigmas, rA, j, m01A, mu2A, sA);
    row_setup(x, means, sigmas, rB, j, m01B, mu2B, sB);

    __syncthreads();   // cons_frag ready

    // ---- main loop: FULLY UNROLLED, all operands register-resident ----
    float dA0[4] = {0.f,0.f,0.f,0.f}, dA1[4] = {0.f,0.f,0.f,0.f};
    float dB0[4] = {0.f,0.f,0.f,0.f}, dB1[4] = {0.f,0.f,0.f,0.f};

    const uint4* frag_l = cons_frag + l;

    #pragma unroll
    for (int o = 0; o < 27; o++) {
        const float qA = m01A[o / 3] * mu2A[o % 3];   // constant idx -> regs
        const float qB = m01B[o / 3] * mu2B[o % 3];

        uint4 a0 = frag_l[(o * 4 + 0) * 32];
        uint4 a1 = frag_l[(o * 4 + 1) * 32];
        uint4 a2 = frag_l[(o * 4 + 2) * 32];
        uint4 a3 = frag_l[(o * 4 + 3) * 32];

        mma_tf32(dA0, &a0.x, qA * sA[0], qA * sA[1]);
        mma_tf32(dB0, &a0.x, qB * sB[0], qB * sB[1]);
        mma_tf32(dA1, &a1.x, qA * sA[2], qA * sA[3]);
        mma_tf32(dB1, &a1.x, qB * sB[2], qB * sB[3]);
        mma_tf32(dA0, &a2.x, qA * sA[4], qA * sA[5]);
        mma_tf32(dB0, &a2.x, qB * sB[4], qB * sB[5]);
        mma_tf32(dA1, &a3.x, qA * sA[6], qA * sA[7]);
        mma_tf32(dB1, &a3.x, qB * sB[6], qB * sB[7]);
    }

    float dA[4], dB[4];
    #pragma unroll
    for (int i = 0; i < 4; i++) { dA[i] = dA0[i] + dA1[i]; dB[i] = dB0[i] + dB1[i]; }

    // ---- scatter D fragments: vbuf[w][batch_n][comp] ----
    // d0=D[g][2j], d1=D[g][2j+1], d2=D[g+8][2j], d3=D[g+8][2j+1]
    const int jj = 2 * j;
    vbuf[w][jj][g]         = dA[0];
    vbuf[w][jj + 1][g]     = dA[1];
    vbuf[w][jj][g + 8]     = dA[2];
    vbuf[w][jj + 1][g + 8] = dA[3];
    vbuf[w][8 + jj][g]         = dB[0];
    vbuf[w][8 + jj + 1][g]     = dB[1];
    vbuf[w][8 + jj][g + 8]     = dB[2];
    vbuf[w][8 + jj + 1][g + 8] = dB[3];
    __syncwarp();

    // ---- epilogue: lanes 0..15 finish one batch row each ----
    if (l < 16) {
        const float* v = vbuf[w][l];
        const int row = Rbase + l;
        float xv[6];
        #pragma unroll
        for (int i = 0; i < 6; i++) xv[i] = x[row * 6 + i];

        const float rden = 1.0f / (v[7] + 1e-6f);
        float skp = v[6], ski = v[14];
        #pragma unroll
        for (int i = 0; i < 6; i++) {
            skp = fmaf(xv[i], v[i],     skp);
            ski = fmaf(xv[i], v[8 + i], ski);
        }
        float2 res;
        res.x = skp * rden;
        res.y = ski * rden;
        *reinterpret_cast<float2*>(out + 2 * row) = res;
    }
}

extern "C" void kernel_launch(void* const* d_in, const int* in_sizes, int n_in,
                              void* d_out, int out_size) {
    const float* x       = (const float*)d_in[0];
    const float* means   = (const float*)d_in[1];
    const float* sigmas  = (const float*)d_in[2];
    const float* cons_kp = (const float*)d_in[3];
    const float* cons_ki = (const float*)d_in[4];
    // d_in[5] = rule_idx: deterministic base-3 digits, baked into the k-permutation
    float* out = (float*)d_out;
    cudaFuncSetAttribute(anfis_tf32_kernel,
                         cudaFuncAttributeMaxDynamicSharedMemorySize, SMEM_BYTES);
    anfis_tf32_kernel<<<GRID, BLOCK, SMEM_BYTES>>>(x, means, sigmas,
                                                   cons_kp, cons_ki, out);
}